// round 5
// baseline (speedup 1.0000x reference)
#include <cuda_runtime.h>
#include <cuda_bf16.h>
#include <cstdint>

// Problem constants
#define Bb 2
#define Ss 2048
#define Dd 1024
#define Hh 16
#define Kk 64
#define BH (Bb*Hh)          // 32
#define SCALE 0.125f        // 1/sqrt(64)
#define NEGF  (-3.402823466e38f)

// ---------------- scratch (static device globals; no allocation) -------------
__device__ float g_Q[(size_t)BH * Ss * Kk];          // [bh, s, k] 16 MB
__device__ float g_K[(size_t)BH * Ss * Kk];          // 16 MB
__device__ float g_V[(size_t)BH * Ss * Kk];          // 16 MB
__device__ float g_heads[(size_t)Bb * Ss * Hh * Kk]; // [b, s, h*K] 16 MB

// 64-FMA micro-kernel helper
#define MICRO_FMA(acc, a0, a1, b0, b1)                                   \
    {                                                                    \
        float _a[8] = {a0.x, a0.y, a0.z, a0.w, a1.x, a1.y, a1.z, a1.w};  \
        float _b[8] = {b0.x, b0.y, b0.z, b0.w, b1.x, b1.y, b1.z, b1.w};  \
        _Pragma("unroll")                                                \
        for (int _i = 0; _i < 8; _i++) {                                 \
            _Pragma("unroll")                                            \
            for (int _j = 0; _j < 8; _j++)                               \
                acc[_i][_j] += _a[_i] * _b[_j];                          \
        }                                                                \
    }

// =============================================================================
// Kernel 1: QKV projection.  X[b] (S x D) @ W[h] (D x 64) + bias
// 128 threads, BM=128, BN=64, BK=32, micro 8x8.
// grid: (S/128, B*H, 3)
// =============================================================================
__global__ __launch_bounds__(128) void qkv_kernel(
    const float* __restrict__ x,
    const float* __restrict__ W_Q, const float* __restrict__ b_Q,
    const float* __restrict__ W_K, const float* __restrict__ b_K,
    const float* __restrict__ W_V, const float* __restrict__ b_V)
{
    const int stile = blockIdx.x;
    const int bh    = blockIdx.y;
    const int which = blockIdx.z;
    const int b = bh / Hh, h = bh % Hh;

    const float* W    = (which == 0) ? W_Q : (which == 1) ? W_K : W_V;
    const float* bias = (which == 0) ? b_Q : (which == 1) ? b_K : b_V;
    float*       out  = (which == 0) ? g_Q : (which == 1) ? g_K : g_V;

    __shared__ float At[32][132];   // A transposed: At[d][row]
    __shared__ float Bs[32][68];    // Bs[d][col]

    const int tid = threadIdx.x;
    const int s0 = stile * 128;
    const float* Ax = x + ((size_t)b * Ss + s0) * Dd;
    const float* Wh = W + (size_t)h * Dd * Kk;

    const int r0 = (tid >> 3) << 3;   // 0..120
    const int c0 = (tid & 7) << 3;    // 0..56

    float acc[8][8];
    #pragma unroll
    for (int i = 0; i < 8; i++)
        #pragma unroll
        for (int j = 0; j < 8; j++) acc[i][j] = 0.f;

    for (int d0 = 0; d0 < Dd; d0 += 32) {
        // load + transpose A tile (128 x 32)
        #pragma unroll
        for (int it = 0; it < 8; it++) {
            const int idx = it * 128 + tid;
            const int row = idx >> 3;
            const int k4  = (idx & 7) << 2;
            const float4 v = *(const float4*)&Ax[(size_t)row * Dd + d0 + k4];
            At[k4 + 0][row] = v.x; At[k4 + 1][row] = v.y;
            At[k4 + 2][row] = v.z; At[k4 + 3][row] = v.w;
        }
        // load B tile (32 x 64)
        #pragma unroll
        for (int it = 0; it < 4; it++) {
            const int idx = it * 128 + tid;
            const int dd = idx >> 4;
            const int c4 = (idx & 15) << 2;
            *(float4*)&Bs[dd][c4] = *(const float4*)&Wh[(size_t)(d0 + dd) * Kk + c4];
        }
        __syncthreads();
        #pragma unroll
        for (int dd = 0; dd < 32; dd++) {
            const float4 a0 = *(const float4*)&At[dd][r0];
            const float4 a1 = *(const float4*)&At[dd][r0 + 4];
            const float4 b0 = *(const float4*)&Bs[dd][c0];
            const float4 b1 = *(const float4*)&Bs[dd][c0 + 4];
            MICRO_FMA(acc, a0, a1, b0, b1);
        }
        __syncthreads();
    }

    float bv[8];
    #pragma unroll
    for (int j = 0; j < 8; j++) bv[j] = bias[h * Kk + c0 + j];

    float* outp = out + ((size_t)bh * Ss + s0) * Kk;
    #pragma unroll
    for (int i = 0; i < 8; i++) {
        float4 o0, o1;
        o0.x = acc[i][0] + bv[0]; o0.y = acc[i][1] + bv[1];
        o0.z = acc[i][2] + bv[2]; o0.w = acc[i][3] + bv[3];
        o1.x = acc[i][4] + bv[4]; o1.y = acc[i][5] + bv[5];
        o1.z = acc[i][6] + bv[6]; o1.w = acc[i][7] + bv[7];
        *(float4*)&outp[(size_t)(r0 + i) * Kk + c0]     = o0;
        *(float4*)&outp[(size_t)(r0 + i) * Kk + c0 + 4] = o1;
    }
}

// =============================================================================
// Kernel 2: scores = mask(Q @ K^T * scale) -> out_scores.
// 256 threads, BM=BN=128, reduction K=64 fully in smem (transposed), micro 8x8.
// grid: (H, 256 tiles, B)  -- heads adjacent so mask tiles hit L2.
// =============================================================================
__global__ __launch_bounds__(256) void scores_kernel(
    const int* __restrict__ mask, float* __restrict__ out_scores)
{
    extern __shared__ float sm[];
    float (*Qt)[132] = (float(*)[132])sm;              // Qt[k][row]
    float (*Kt)[132] = (float(*)[132])(sm + 64 * 132); // Kt[k][col]

    const int h  = blockIdx.x;
    const int b  = blockIdx.z;
    const int bh = b * Hh + h;
    const int st = blockIdx.y & 15;
    const int tt = blockIdx.y >> 4;
    const int s0 = st * 128;
    const int t0 = tt * 128;
    const int tid = threadIdx.x;

    const float* Qg = g_Q + ((size_t)bh * Ss + s0) * Kk;
    const float* Kg = g_K + ((size_t)bh * Ss + t0) * Kk;

    // load + transpose Q and K tiles (each 128 x 64)
    #pragma unroll
    for (int it = 0; it < 8; it++) {
        const int idx = it * 256 + tid;
        const int row = idx >> 4;
        const int k4  = (idx & 15) << 2;
        const float4 q = *(const float4*)&Qg[(size_t)row * Kk + k4];
        Qt[k4 + 0][row] = q.x; Qt[k4 + 1][row] = q.y;
        Qt[k4 + 2][row] = q.z; Qt[k4 + 3][row] = q.w;
        const float4 k = *(const float4*)&Kg[(size_t)row * Kk + k4];
        Kt[k4 + 0][row] = k.x; Kt[k4 + 1][row] = k.y;
        Kt[k4 + 2][row] = k.z; Kt[k4 + 3][row] = k.w;
    }
    __syncthreads();

    const int r0 = (tid >> 4) << 3;   // query rows
    const int c0 = (tid & 15) << 3;   // key cols

    float acc[8][8];
    #pragma unroll
    for (int i = 0; i < 8; i++)
        #pragma unroll
        for (int j = 0; j < 8; j++) acc[i][j] = 0.f;

    #pragma unroll 8
    for (int k = 0; k < Kk; k++) {
        const float4 a0 = *(const float4*)&Qt[k][r0];
        const float4 a1 = *(const float4*)&Qt[k][r0 + 4];
        const float4 b0 = *(const float4*)&Kt[k][c0];
        const float4 b1 = *(const float4*)&Kt[k][c0 + 4];
        MICRO_FMA(acc, a0, a1, b0, b1);
    }

    // epilogue: mask + scale + store
    #pragma unroll
    for (int i = 0; i < 8; i++) {
        const int s = s0 + r0 + i;
        const int* mrow = mask + ((size_t)b * Ss + s) * Ss + t0;
        const int4 m0 = *(const int4*)&mrow[c0];
        const int4 m1 = *(const int4*)&mrow[c0 + 4];
        float4 o0, o1;
        o0.x = m0.x ? acc[i][0] * SCALE : NEGF;
        o0.y = m0.y ? acc[i][1] * SCALE : NEGF;
        o0.z = m0.z ? acc[i][2] * SCALE : NEGF;
        o0.w = m0.w ? acc[i][3] * SCALE : NEGF;
        o1.x = m1.x ? acc[i][4] * SCALE : NEGF;
        o1.y = m1.y ? acc[i][5] * SCALE : NEGF;
        o1.z = m1.z ? acc[i][6] * SCALE : NEGF;
        o1.w = m1.w ? acc[i][7] * SCALE : NEGF;
        float* orow = out_scores + ((size_t)bh * Ss + s) * Ss + t0;
        *(float4*)&orow[c0]     = o0;
        *(float4*)&orow[c0 + 4] = o1;
    }
}

// =============================================================================
// Kernel 3: in-place row softmax over out_scores. 256 threads, 1 row per block.
// grid: (BH * S)
// =============================================================================
__global__ __launch_bounds__(256) void softmax_kernel(float* __restrict__ scores)
{
    __shared__ float red[8];
    __shared__ float bcast;

    float4* row = (float4*)(scores + (size_t)blockIdx.x * Ss);
    const int tid = threadIdx.x;
    const int lane = tid & 31, warp = tid >> 5;

    float4 v0 = row[tid];
    float4 v1 = row[tid + 256];

    // max
    float mx = fmaxf(fmaxf(fmaxf(v0.x, v0.y), fmaxf(v0.z, v0.w)),
                     fmaxf(fmaxf(v1.x, v1.y), fmaxf(v1.z, v1.w)));
    #pragma unroll
    for (int o = 16; o > 0; o >>= 1) mx = fmaxf(mx, __shfl_xor_sync(0xffffffffu, mx, o));
    if (lane == 0) red[warp] = mx;
    __syncthreads();
    if (tid == 0) {
        float m = red[0];
        #pragma unroll
        for (int i = 1; i < 8; i++) m = fmaxf(m, red[i]);
        bcast = m;
    }
    __syncthreads();
    mx = bcast;

    // exp + sum
    v0.x = __expf(v0.x - mx); v0.y = __expf(v0.y - mx);
    v0.z = __expf(v0.z - mx); v0.w = __expf(v0.w - mx);
    v1.x = __expf(v1.x - mx); v1.y = __expf(v1.y - mx);
    v1.z = __expf(v1.z - mx); v1.w = __expf(v1.w - mx);
    float sum = v0.x + v0.y + v0.z + v0.w + v1.x + v1.y + v1.z + v1.w;
    #pragma unroll
    for (int o = 16; o > 0; o >>= 1) sum += __shfl_xor_sync(0xffffffffu, sum, o);
    __syncthreads();
    if (lane == 0) red[warp] = sum;
    __syncthreads();
    if (tid == 0) {
        float s = 0.f;
        #pragma unroll
        for (int i = 0; i < 8; i++) s += red[i];
        bcast = 1.0f / s;
    }
    __syncthreads();
    const float inv = bcast;

    v0.x *= inv; v0.y *= inv; v0.z *= inv; v0.w *= inv;
    v1.x *= inv; v1.y *= inv; v1.z *= inv; v1.w *= inv;
    row[tid]       = v0;
    row[tid + 256] = v1;
}

// =============================================================================
// Kernel 4: heads = P @ V per (b,h).  M=2048(s), N=64(k), red=2048(t).
// 128 threads, BM=128, BN=64, BK=32, micro 8x8.
// grid: (S/128, BH)
// =============================================================================
__global__ __launch_bounds__(128) void pv_kernel(
    const float* __restrict__ probs)
{
    __shared__ float Pt[32][132];   // Pt[t][row]
    __shared__ float Vs[32][68];    // Vs[t][col]

    const int bh = blockIdx.y;
    const int b = bh / Hh, h = bh % Hh;
    const int s0 = blockIdx.x * 128;
    const int tid = threadIdx.x;

    const float* Pg = probs + ((size_t)bh * Ss + s0) * Ss;
    const float* Vg = g_V + (size_t)bh * Ss * Kk;

    const int r0 = (tid >> 3) << 3;
    const int c0 = (tid & 7) << 3;

    float acc[8][8];
    #pragma unroll
    for (int i = 0; i < 8; i++)
        #pragma unroll
        for (int j = 0; j < 8; j++) acc[i][j] = 0.f;

    for (int t0 = 0; t0 < Ss; t0 += 32) {
        // load + transpose P tile (128 x 32)
        #pragma unroll
        for (int it = 0; it < 8; it++) {
            const int idx = it * 128 + tid;
            const int row = idx >> 3;
            const int q4  = (idx & 7) << 2;
            const float4 v = *(const float4*)&Pg[(size_t)row * Ss + t0 + q4];
            Pt[q4 + 0][row] = v.x; Pt[q4 + 1][row] = v.y;
            Pt[q4 + 2][row] = v.z; Pt[q4 + 3][row] = v.w;
        }
        // load V tile (32 x 64)
        #pragma unroll
        for (int it = 0; it < 4; it++) {
            const int idx = it * 128 + tid;
            const int tt = idx >> 4;
            const int c4 = (idx & 15) << 2;
            *(float4*)&Vs[tt][c4] = *(const float4*)&Vg[(size_t)(t0 + tt) * Kk + c4];
        }
        __syncthreads();
        #pragma unroll
        for (int tt = 0; tt < 32; tt++) {
            const float4 a0 = *(const float4*)&Pt[tt][r0];
            const float4 a1 = *(const float4*)&Pt[tt][r0 + 4];
            const float4 b0 = *(const float4*)&Vs[tt][c0];
            const float4 b1 = *(const float4*)&Vs[tt][c0 + 4];
            MICRO_FMA(acc, a0, a1, b0, b1);
        }
        __syncthreads();
    }

    #pragma unroll
    for (int i = 0; i < 8; i++) {
        float* orow = g_heads + ((size_t)(b * Ss + s0 + r0 + i)) * (Hh * Kk) + h * Kk;
        float4 o0, o1;
        o0.x = acc[i][0]; o0.y = acc[i][1]; o0.z = acc[i][2]; o0.w = acc[i][3];
        o1.x = acc[i][4]; o1.y = acc[i][5]; o1.z = acc[i][6]; o1.w = acc[i][7];
        *(float4*)&orow[c0]     = o0;
        *(float4*)&orow[c0 + 4] = o1;
    }
}

// =============================================================================
// Kernel 5: out = heads (4096 x 1024) @ W_proj (1024 x 1024) + b_proj.
// 128 threads, BM=128, BN=64, BK=32, micro 8x8.
// grid: (1024/64, 4096/128)
// =============================================================================
__global__ __launch_bounds__(128) void proj_kernel(
    const float* __restrict__ Wp, const float* __restrict__ bp,
    float* __restrict__ out)
{
    __shared__ float At[32][132];
    __shared__ float Bs[32][68];

    const int tid = threadIdx.x;
    const int n0 = blockIdx.x * 64;
    const int m0 = blockIdx.y * 128;
    const int HK = Hh * Kk;   // 1024

    const float* A = g_heads + (size_t)m0 * HK;

    const int r0 = (tid >> 3) << 3;
    const int c0 = (tid & 7) << 3;

    float acc[8][8];
    #pragma unroll
    for (int i = 0; i < 8; i++)
        #pragma unroll
        for (int j = 0; j < 8; j++) acc[i][j] = 0.f;

    for (int d0 = 0; d0 < HK; d0 += 32) {
        #pragma unroll
        for (int it = 0; it < 8; it++) {
            const int idx = it * 128 + tid;
            const int row = idx >> 3;
            const int k4  = (idx & 7) << 2;
            const float4 v = *(const float4*)&A[(size_t)row * HK + d0 + k4];
            At[k4 + 0][row] = v.x; At[k4 + 1][row] = v.y;
            At[k4 + 2][row] = v.z; At[k4 + 3][row] = v.w;
        }
        #pragma unroll
        for (int it = 0; it < 4; it++) {
            const int idx = it * 128 + tid;
            const int dd = idx >> 4;
            const int c4 = (idx & 15) << 2;
            *(float4*)&Bs[dd][c4] = *(const float4*)&Wp[(size_t)(d0 + dd) * Dd + n0 + c4];
        }
        __syncthreads();
        #pragma unroll
        for (int dd = 0; dd < 32; dd++) {
            const float4 a0 = *(const float4*)&At[dd][r0];
            const float4 a1 = *(const float4*)&At[dd][r0 + 4];
            const float4 b0 = *(const float4*)&Bs[dd][c0];
            const float4 b1 = *(const float4*)&Bs[dd][c0 + 4];
            MICRO_FMA(acc, a0, a1, b0, b1);
        }
        __syncthreads();
    }

    float bv[8];
    #pragma unroll
    for (int j = 0; j < 8; j++) bv[j] = bp[n0 + c0 + j];

    #pragma unroll
    for (int i = 0; i < 8; i++) {
        float4 o0, o1;
        o0.x = acc[i][0] + bv[0]; o0.y = acc[i][1] + bv[1];
        o0.z = acc[i][2] + bv[2]; o0.w = acc[i][3] + bv[3];
        o1.x = acc[i][4] + bv[4]; o1.y = acc[i][5] + bv[5];
        o1.z = acc[i][6] + bv[6]; o1.w = acc[i][7] + bv[7];
        *(float4*)&out[(size_t)(m0 + r0 + i) * Dd + n0 + c0]     = o0;
        *(float4*)&out[(size_t)(m0 + r0 + i) * Dd + n0 + c0 + 4] = o1;
    }
}

// =============================================================================
extern "C" void kernel_launch(void* const* d_in, const int* in_sizes, int n_in,
                              void* d_out, int out_size)
{
    const float* x      = (const float*)d_in[0];
    const float* W_Q    = (const float*)d_in[1];
    const float* b_Q    = (const float*)d_in[2];
    const float* W_K    = (const float*)d_in[3];
    const float* b_K    = (const float*)d_in[4];
    const float* W_V    = (const float*)d_in[5];
    const float* b_V    = (const float*)d_in[6];
    const float* W_proj = (const float*)d_in[7];
    const float* b_proj = (const float*)d_in[8];
    const int*   amask  = (const int*)d_in[9];

    float* out        = (float*)d_out;                       // [B,S,D]
    float* out_scores = out + (size_t)Bb * Ss * Dd;          // [B,H,S,S]

    // 1) QKV projections
    {
        dim3 grid(Ss / 128, BH, 3);
        qkv_kernel<<<grid, 128>>>(x, W_Q, b_Q, W_K, b_K, W_V, b_V);
    }

    // 2) masked, scaled scores -> out_scores
    {
        const int smem = 2 * 64 * 132 * (int)sizeof(float);   // 67.6 KB
        cudaFuncSetAttribute(scores_kernel, cudaFuncAttributeMaxDynamicSharedMemorySize, smem);
        dim3 grid(Hh, (Ss / 128) * (Ss / 128), Bb);
        scores_kernel<<<grid, 256, smem>>>(amask, out_scores);
    }

    // 3) in-place softmax
    {
        softmax_kernel<<<BH * Ss, 256>>>(out_scores);
    }

    // 4) P @ V -> g_heads
    {
        dim3 grid(Ss / 128, BH);
        pv_kernel<<<grid, 128>>>(out_scores);
    }

    // 5) output projection
    {
        dim3 grid(Dd / 64, (Bb * Ss) / 128);
        proj_kernel<<<grid, 128>>>(W_proj, b_proj, out);
    }
}